// round 3
// baseline (speedup 1.0000x reference)
#include <cuda_runtime.h>
#include <math.h>

#define BB 64
#define TT 512
#define VV 256
#define MM 1024
#define G4 4096   // 4*MM

// ---- static device scratch (no cudaMalloc allowed) ----
__device__ float g_pre[(size_t)BB * TT * G4];    // 512 MB pre-activations (reused layer0/1)
__device__ float g_hseq[(size_t)BB * TT * MM];   // 128 MB h sequence (reused layer0/1)
__device__ float g_hbuf[2][BB * MM];             // h ping-pong for recurrence
__device__ float g_cfin[2 * BB * MM];            // final c per layer
__device__ float g_hfin[2 * BB * MM];            // final h per layer
__device__ unsigned g_bar_count;                 // zero-init
__device__ unsigned g_bar_gen;                   // zero-init, monotonic (replay-safe)

__device__ __forceinline__ float sigmoidf_(float x) {
    return 1.0f / (1.0f + __expf(-x));
}

// ---------------------------------------------------------------------------
// Software grid barrier. All CTAs co-resident (grid=128 <= 148 SMs, 1 CTA/SM).
// Generation counter is monotonic -> safe across graph replays.
// ---------------------------------------------------------------------------
__device__ __forceinline__ void grid_barrier(unsigned expected) {
    __syncthreads();
    if (threadIdx.x == 0) {
        __threadfence();
        unsigned gen = *(volatile unsigned*)&g_bar_gen;   // read BEFORE arriving
        unsigned a = atomicAdd(&g_bar_count, 1);
        if (a == expected - 1) {
            g_bar_count = 0;
            __threadfence();
            atomicAdd(&g_bar_gen, 1);                     // release
        } else {
            while (*(volatile unsigned*)&g_bar_gen == gen) { }
        }
        __threadfence();
    }
    __syncthreads();
}

// ---------------------------------------------------------------------------
// Generic fp32 GEMM + bias: C[M][N] = A[M][K] @ W[K][N] + bias[N]
// BM=64, BN=64, BK=16, 256 threads, 4x4 microtile. (numerics validated R1)
// ---------------------------------------------------------------------------
__global__ void gemm_bias_kernel(const float* __restrict__ A,
                                 const float* __restrict__ W,
                                 const float* __restrict__ bias,
                                 float* __restrict__ C,
                                 int M, int N, int K) {
    __shared__ float As[16][64];   // [k][m]
    __shared__ float Bs[16][64];   // [k][n]
    int tid = threadIdx.x;
    int n0 = blockIdx.x * 64;
    int m0 = blockIdx.y * 64;
    int tx = tid & 15;
    int ty = tid >> 4;
    float acc[4][4] = {};

    int a_row = tid >> 2;
    int a_k   = (tid & 3) * 4;
    int b_row = tid >> 4;
    int b_c   = (tid & 15) * 4;

    for (int k0 = 0; k0 < K; k0 += 16) {
        float4 av = *(const float4*)&A[(size_t)(m0 + a_row) * K + k0 + a_k];
        As[a_k + 0][a_row] = av.x;
        As[a_k + 1][a_row] = av.y;
        As[a_k + 2][a_row] = av.z;
        As[a_k + 3][a_row] = av.w;
        *(float4*)&Bs[b_row][b_c] =
            *(const float4*)&W[(size_t)(k0 + b_row) * N + n0 + b_c];
        __syncthreads();
#pragma unroll
        for (int kk = 0; kk < 16; kk++) {
            float4 a = *(const float4*)&As[kk][ty * 4];
            float4 b = *(const float4*)&Bs[kk][tx * 4];
            acc[0][0] += a.x * b.x; acc[0][1] += a.x * b.y;
            acc[0][2] += a.x * b.z; acc[0][3] += a.x * b.w;
            acc[1][0] += a.y * b.x; acc[1][1] += a.y * b.y;
            acc[1][2] += a.y * b.z; acc[1][3] += a.y * b.w;
            acc[2][0] += a.z * b.x; acc[2][1] += a.z * b.y;
            acc[2][2] += a.z * b.z; acc[2][3] += a.z * b.w;
            acc[3][0] += a.w * b.x; acc[3][1] += a.w * b.y;
            acc[3][2] += a.w * b.z; acc[3][3] += a.w * b.w;
        }
        __syncthreads();
    }

    float4 bv = *(const float4*)&bias[n0 + tx * 4];
#pragma unroll
    for (int i = 0; i < 4; i++) {
        float4 r;
        r.x = acc[i][0] + bv.x;
        r.y = acc[i][1] + bv.y;
        r.z = acc[i][2] + bv.z;
        r.w = acc[i][3] + bv.w;
        *(float4*)&C[(size_t)(m0 + ty * 4 + i) * N + n0 + tx * 4] = r;
    }
}

// ---------------------------------------------------------------------------
// Persistent LSTM recurrence for one layer: all 512 steps in ONE launch.
// Grid = 128 CTAs (co-resident), 256 threads.
// CTA tile: 32 batch rows x (16 mem x 4 gates) = 32x64 z-columns.
// Two intra-CTA K-split groups (kg=0: K[0,512), kg=1: K[512,1024)),
// each 128 threads, 4x4 microtile (4 rows x 4 gates of one m).
// c lives in registers for all 512 steps. h ping-pongs in g_hbuf.
// One grid barrier per step.
// ---------------------------------------------------------------------------
__global__ void __launch_bounds__(256, 1)
lstm_persistent_kernel(const float* __restrict__ state,  // [B, 2*MM] (c | h)
                       const float* __restrict__ Wh,     // [MM][G4] recurrent slice
                       const float* __restrict__ pre,    // [B][T][G4]
                       float* __restrict__ hseq,         // [B][T][MM]
                       float* __restrict__ cfin,         // [B*MM]
                       float* __restrict__ hfin) {       // [B*MM]
    __shared__ float As[2][16][32];
    __shared__ float Bs[2][16][64];

    int tid = threadIdx.x;
    int kg  = tid >> 7;          // K-split group 0/1
    int lt  = tid & 127;
    int mt0 = (blockIdx.x & 63) << 4;   // mem-slice base
    int r0  = (blockIdx.x >> 6) << 5;   // batch-row base
    int rg  = lt >> 4;           // row group 0..7 (4 rows each)
    int cg  = lt & 15;           // m within slice
    int m   = mt0 + cg;

    int a_row = lt >> 2;         // 0..31
    int a_k   = (lt & 3) << 2;   // 0,4,8,12
    int b_k   = lt >> 3;         // 0..15
    int b_q   = lt & 7;          // 0..7

    // c state in registers (meaningful for kg==0; owner is fixed for all t)
    float c_reg[4];
#pragma unroll
    for (int i = 0; i < 4; i++)
        c_reg[i] = state[(size_t)(r0 + rg * 4 + i) * (2 * MM) + m];

    int kbase = kg << 9;         // 0 or 512
    float* red = &Bs[0][0][0];   // 8KB reduction buffer (reuses Bs)

    for (int t = 0; t < TT; t++) {
        const float* hsrc;
        size_t hstr;
        if (t == 0) { hsrc = state + MM; hstr = 2 * MM; }
        else        { hsrc = g_hbuf[t & 1]; hstr = MM; }

        float acc[4][4] = {};

        for (int k0 = 0; k0 < 512; k0 += 16) {
            // A: 32 rows x 16 k per group
            float4 av = *(const float4*)&hsrc[(size_t)(r0 + a_row) * hstr +
                                              kbase + k0 + a_k];
            As[kg][a_k + 0][a_row] = av.x;
            As[kg][a_k + 1][a_row] = av.y;
            As[kg][a_k + 2][a_row] = av.z;
            As[kg][a_k + 3][a_row] = av.w;
            // B: 16 k-rows x 64 cols (gate-interleaved cc = j*4 + g)
#pragma unroll
            for (int rep = 0; rep < 2; rep++) {
                int q  = b_q + rep * 8;
                int g  = q >> 2;
                int j4 = (q & 3) << 2;
                float4 bv = *(const float4*)&Wh[(size_t)(kbase + k0 + b_k) * G4 +
                                                g * MM + mt0 + j4];
                Bs[kg][b_k][(j4 + 0) * 4 + g] = bv.x;
                Bs[kg][b_k][(j4 + 1) * 4 + g] = bv.y;
                Bs[kg][b_k][(j4 + 2) * 4 + g] = bv.z;
                Bs[kg][b_k][(j4 + 3) * 4 + g] = bv.w;
            }
            __syncthreads();
#pragma unroll
            for (int kk = 0; kk < 16; kk++) {
                float4 a = *(const float4*)&As[kg][kk][rg * 4];
                float4 b = *(const float4*)&Bs[kg][kk][cg * 4];
                acc[0][0] += a.x * b.x; acc[0][1] += a.x * b.y;
                acc[0][2] += a.x * b.z; acc[0][3] += a.x * b.w;
                acc[1][0] += a.y * b.x; acc[1][1] += a.y * b.y;
                acc[1][2] += a.y * b.z; acc[1][3] += a.y * b.w;
                acc[2][0] += a.z * b.x; acc[2][1] += a.z * b.y;
                acc[2][2] += a.z * b.z; acc[2][3] += a.z * b.w;
                acc[3][0] += a.w * b.x; acc[3][1] += a.w * b.y;
                acc[3][2] += a.w * b.z; acc[3][3] += a.w * b.w;
            }
            __syncthreads();
        }

        // combine the two K-halves through smem
        if (kg == 1) {
#pragma unroll
            for (int i = 0; i < 4; i++)
#pragma unroll
                for (int j = 0; j < 4; j++)
                    red[lt * 16 + i * 4 + j] = acc[i][j];
        }
        __syncthreads();

        if (kg == 0) {
#pragma unroll
            for (int i = 0; i < 4; i++) {
                int b = r0 + rg * 4 + i;
                size_t pb = ((size_t)b * TT + t) * (size_t)G4 + m;
                float zi = acc[i][0] + red[lt * 16 + i * 4 + 0] + pre[pb];
                float zj = acc[i][1] + red[lt * 16 + i * 4 + 1] + pre[pb + MM];
                float zf = acc[i][2] + red[lt * 16 + i * 4 + 2] + pre[pb + 2 * MM];
                float zo = acc[i][3] + red[lt * 16 + i * 4 + 3] + pre[pb + 3 * MM];
                float fg = sigmoidf_(zf + 1.0f);   // FORGET_BIAS
                float ig = sigmoidf_(zi);
                float og = sigmoidf_(zo);
                float cv = c_reg[i] * fg + ig * tanhf(zj);
                c_reg[i] = cv;
                float hv = tanhf(cv) * og;
                g_hbuf[(t + 1) & 1][(size_t)b * MM + m] = hv;
                hseq[((size_t)b * TT + t) * (size_t)MM + m] = hv;
                if (t == TT - 1) {
                    cfin[(size_t)b * MM + m] = cv;
                    hfin[(size_t)b * MM + m] = hv;
                }
            }
        }
        // barrier: orders h writes (t) before h reads (t+1), and protects
        // the red/Bs reuse at the top of the next iteration.
        grid_barrier(gridDim.x);
    }
}

// ---------------------------------------------------------------------------
// final_state: out layout [2][BB][2*MM], row = concat(c, h)
// ---------------------------------------------------------------------------
__global__ void final_state_kernel(float* __restrict__ out) {
    int i = blockIdx.x * blockDim.x + threadIdx.x;
    if (i < 2 * BB * 2 * MM) {
        int l = i / (BB * 2 * MM);
        int r = i % (BB * 2 * MM);
        int b = r / (2 * MM);
        int mm = r % (2 * MM);
        float v = (mm < MM) ? g_cfin[l * BB * MM + b * MM + mm]
                            : g_hfin[l * BB * MM + b * MM + (mm - MM)];
        out[i] = v;
    }
}

// ---------------------------------------------------------------------------
extern "C" void kernel_launch(void* const* d_in, const int* in_sizes, int n_in,
                              void* d_out, int out_size) {
    const float* x      = (const float*)d_in[0];  // [B,T,V]
    const float* state0 = (const float*)d_in[1];  // [B,2*MM]
    const float* state1 = (const float*)d_in[2];
    const float* W0     = (const float*)d_in[3];  // [V+MM, 4*MM]
    const float* b0     = (const float*)d_in[4];
    const float* W1     = (const float*)d_in[5];  // [2*MM, 4*MM]
    const float* b1     = (const float*)d_in[6];
    const float* W_out  = (const float*)d_in[7];  // [MM, V]
    const float* b_out  = (const float*)d_in[8];
    float* out = (float*)d_out;

    float *pre, *hseq, *cfin, *hfin;
    cudaGetSymbolAddress((void**)&pre,  g_pre);
    cudaGetSymbolAddress((void**)&hseq, g_hseq);
    cudaGetSymbolAddress((void**)&cfin, g_cfin);
    cudaGetSymbolAddress((void**)&hfin, g_hfin);

    // 1) pre0 = x @ W0[:V,:] + b0
    gemm_bias_kernel<<<dim3(G4 / 64, (BB * TT) / 64), 256>>>(
        x, W0, b0, pre, BB * TT, G4, VV);

    // 2) layer-0 recurrence: one persistent launch, 512 steps
    lstm_persistent_kernel<<<128, 256>>>(
        state0, W0 + (size_t)VV * G4, pre, hseq, cfin, hfin);

    // 3) pre1 = h0_seq @ W1[:MM,:] + b1
    gemm_bias_kernel<<<dim3(G4 / 64, (BB * TT) / 64), 256>>>(
        hseq, W1, b1, pre, BB * TT, G4, MM);

    // 4) layer-1 recurrence (hseq overwritten in place; pre1 already consumed it)
    lstm_persistent_kernel<<<128, 256>>>(
        state1, W1 + (size_t)MM * G4, pre, hseq,
        cfin + BB * MM, hfin + BB * MM);

    // 5) outputs = h1_seq @ W_out + b_out
    gemm_bias_kernel<<<dim3(VV / 64, (BB * TT) / 64), 256>>>(
        hseq, W_out, b_out, out, BB * TT, VV, MM);

    // 6) final_state -> d_out[B*T*V : ]
    final_state_kernel<<<(2 * BB * 2 * MM + 255) / 256, 256>>>(
        out + (size_t)BB * TT * VV);
}

// round 10
// speedup vs baseline: 1.1427x; 1.1427x over previous
#include <cuda_runtime.h>
#include <cuda_bf16.h>
#include <math.h>
#include <stdint.h>

#define BB 64
#define TT 512
#define VV 256
#define MM 1024
#define G4 4096

// ---- static device scratch (no cudaMalloc allowed) ----
__device__ float g_pre[(size_t)BB * TT * G4];    // 512 MB pre-activations
__device__ float g_hseq[(size_t)BB * TT * MM];   // 128 MB h sequence
__device__ float g_hbuf[2][BB * MM];
__device__ float g_cfin[2 * BB * MM];
__device__ float g_hfin[2 * BB * MM];
__device__ unsigned g_bar_count;
__device__ unsigned g_bar_gen;
// split-bf16 operands
__device__ __nv_bfloat16 g_Ahi[(size_t)BB * TT * MM];
__device__ __nv_bfloat16 g_Alo[(size_t)BB * TT * MM];
__device__ __nv_bfloat16 g_Wt0hi[G4 * VV], g_Wt0lo[G4 * VV];
__device__ __nv_bfloat16 g_Wt1hi[(size_t)G4 * MM], g_Wt1lo[(size_t)G4 * MM];
__device__ __nv_bfloat16 g_WtOhi[VV * MM], g_WtOlo[VV * MM];

__device__ __forceinline__ float sigmoidf_(float x) {
    return 1.0f / (1.0f + __expf(-x));
}

__device__ __forceinline__ uint32_t smem_u32(const void* p) {
    uint32_t a;
    asm("{ .reg .u64 t; cvta.to.shared.u64 t, %1; cvt.u32.u64 %0, t; }"
        : "=r"(a) : "l"(p));
    return a;
}

// ---------------- prep kernels ----------------
__global__ void split_kernel(const float* __restrict__ in,
                             __nv_bfloat16* __restrict__ hi,
                             __nv_bfloat16* __restrict__ lo, size_t n) {
    size_t i = (size_t)blockIdx.x * blockDim.x + threadIdx.x;
    if (i < n) {
        float v = in[i];
        __nv_bfloat16 h = __float2bfloat16_rn(v);
        hi[i] = h;
        lo[i] = __float2bfloat16_rn(v - __bfloat162float(h));
    }
}

// W[k][ldin] (first K rows, N cols) -> T[n][K] hi/lo
__global__ void transpose_split_kernel(const float* __restrict__ W, int ldin,
                                       __nv_bfloat16* __restrict__ Thi,
                                       __nv_bfloat16* __restrict__ Tlo,
                                       int K, int N) {
    __shared__ float tile[32][33];
    int k0 = blockIdx.y * 32, n0 = blockIdx.x * 32;
    int tx = threadIdx.x & 31, ty = threadIdx.x >> 5;
    for (int i = 0; i < 32; i += 8)
        tile[ty + i][tx] = W[(size_t)(k0 + ty + i) * ldin + n0 + tx];
    __syncthreads();
    for (int i = 0; i < 32; i += 8) {
        int n = n0 + ty + i, k = k0 + tx;
        float v = tile[tx][ty + i];
        __nv_bfloat16 h = __float2bfloat16_rn(v);
        Thi[(size_t)n * K + k] = h;
        Tlo[(size_t)n * K + k] = __float2bfloat16_rn(v - __bfloat162float(h));
    }
}

// ---------------------------------------------------------------------------
// mma.sync split-bf16 GEMM:  C[M][N] = A[m][K] x (B[n][K])^T + bias
// CTA 128x128, 8 warps (2x4), warp tile 64x32, BK=32, cp.async 2-stage.
// 3 passes: AhiBhi + AhiBlo + AloBhi, fp32 register accumulators.
// ---------------------------------------------------------------------------
#define LDS 40                     // 32 k + 8 pad (bf16 elems)
#define TILE_E (128 * LDS)         // elements per tile
#define GT_SMEM (2 * 4 * TILE_E * 2)   // 81920 bytes

__device__ __forceinline__ void issue_chunk(
    __nv_bfloat16* st,
    const __nv_bfloat16* Ahi, const __nv_bfloat16* Alo,
    const __nv_bfloat16* Bhi, const __nv_bfloat16* Blo,
    int m0, int n0, int Ktot, int k0, int tid) {
    const __nv_bfloat16* srcs[4] = {Ahi, Alo, Bhi, Blo};
#pragma unroll
    for (int t = 0; t < 4; t++) {
        int rbase = (t < 2) ? m0 : n0;
        const __nv_bfloat16* gp = srcs[t];
#pragma unroll
        for (int i = 0; i < 2; i++) {
            int u = i * 256 + tid;                 // 0..511
            int row = u >> 2;                      // 0..127  (4 loads per row)
            int koff = (u & 3) * 8;                // 0,8,16,24
            uint32_t d = smem_u32(st + t * TILE_E + row * LDS + koff);
            const void* s = gp + (size_t)(rbase + row) * Ktot + k0 + koff;
            asm volatile("cp.async.ca.shared.global [%0], [%1], 16;"
                         :: "r"(d), "l"(s) : "memory");
        }
    }
    asm volatile("cp.async.commit_group;" ::: "memory");
}

__device__ __forceinline__ void mma_bf16(float* c, const uint32_t* a,
                                         const uint32_t* b) {
    asm volatile(
        "mma.sync.aligned.m16n8k16.row.col.f32.bf16.bf16.f32 "
        "{%0,%1,%2,%3}, {%4,%5,%6,%7}, {%8,%9}, {%0,%1,%2,%3};"
        : "+f"(c[0]), "+f"(c[1]), "+f"(c[2]), "+f"(c[3])
        : "r"(a[0]), "r"(a[1]), "r"(a[2]), "r"(a[3]), "r"(b[0]), "r"(b[1]));
}

__global__ void __launch_bounds__(256, 1)
gemmT_kernel(const __nv_bfloat16* __restrict__ Ahi, const __nv_bfloat16* __restrict__ Alo,
             const __nv_bfloat16* __restrict__ Bhi, const __nv_bfloat16* __restrict__ Blo,
             const float* __restrict__ bias, float* __restrict__ C,
             int Ktot, int Ncols) {
    extern __shared__ __nv_bfloat16 sm[];
    int tid = threadIdx.x, warp = tid >> 5, lane = tid & 31;
    int m0 = blockIdx.y << 7, n0 = blockIdx.x << 7;
    int wm = warp >> 2, wn = warp & 3;
    uint32_t sb = smem_u32(sm);

    float acc[4][4][4];
#pragma unroll
    for (int i = 0; i < 4; i++)
#pragma unroll
        for (int j = 0; j < 4; j++)
#pragma unroll
            for (int q = 0; q < 4; q++) acc[i][j][q] = 0.0f;

    // ldmatrix per-lane address components
    int q4 = lane >> 3, r8 = lane & 7;
    int aro = (q4 & 1) * 8 + r8;       // A row offset within 16 (= lane%16)
    int aco = (q4 >> 1) * 8;           // A col offset (= (lane/16)*8)
    int bj = (lane & 15) >> 3;         // B k-half
    int bro = lane & 7;                // B row within 8

    int nchunk = Ktot >> 5;
    issue_chunk(sm, Ahi, Alo, Bhi, Blo, m0, n0, Ktot, 0, tid);

    for (int ch = 0; ch < nchunk; ch++) {
        if (ch + 1 < nchunk) {
            issue_chunk(sm + ((ch + 1) & 1) * 4 * TILE_E,
                        Ahi, Alo, Bhi, Blo, m0, n0, Ktot, (ch + 1) << 5, tid);
            asm volatile("cp.async.wait_group 1;" ::: "memory");
        } else {
            asm volatile("cp.async.wait_group 0;" ::: "memory");
        }
        __syncthreads();

        uint32_t stb = sb + (uint32_t)((ch & 1) * 4 * TILE_E * 2);
#pragma unroll
        for (int s = 0; s < 2; s++) {
            uint32_t ah[4][4], al[4][4], bh[4][2], bl[4][2];
#pragma unroll
            for (int mi = 0; mi < 4; mi++) {
                uint32_t ad = stb +
                    (uint32_t)(((wm * 64 + mi * 16 + aro) * LDS + s * 16 + aco) * 2);
                asm volatile(
                    "ldmatrix.sync.aligned.m8n8.x4.shared.b16 {%0,%1,%2,%3}, [%4];"
                    : "=r"(ah[mi][0]), "=r"(ah[mi][1]), "=r"(ah[mi][2]), "=r"(ah[mi][3])
                    : "r"(ad));
                asm volatile(
                    "ldmatrix.sync.aligned.m8n8.x4.shared.b16 {%0,%1,%2,%3}, [%4];"
                    : "=r"(al[mi][0]), "=r"(al[mi][1]), "=r"(al[mi][2]), "=r"(al[mi][3])
                    : "r"(ad + TILE_E * 2));
            }
#pragma unroll
            for (int ni = 0; ni < 4; ni++) {
                uint32_t bd = stb + (uint32_t)((2 * TILE_E +
                    (wn * 32 + ni * 8 + bro) * LDS + s * 16 + bj * 8) * 2);
                asm volatile(
                    "ldmatrix.sync.aligned.m8n8.x2.shared.b16 {%0,%1}, [%2];"
                    : "=r"(bh[ni][0]), "=r"(bh[ni][1]) : "r"(bd));
                asm volatile(
                    "ldmatrix.sync.aligned.m8n8.x2.shared.b16 {%0,%1}, [%2];"
                    : "=r"(bl[ni][0]), "=r"(bl[ni][1]) : "r"(bd + TILE_E * 2));
            }
#pragma unroll
            for (int mi = 0; mi < 4; mi++)
#pragma unroll
                for (int ni = 0; ni < 4; ni++) {
                    mma_bf16(acc[mi][ni], ah[mi], bh[ni]);
                    mma_bf16(acc[mi][ni], ah[mi], bl[ni]);
                    mma_bf16(acc[mi][ni], al[mi], bh[ni]);
                }
        }
        __syncthreads();
    }

    // epilogue: bias + store (c0,c1 -> row g; c2,c3 -> row g+8; cols 2t,2t+1)
    int g = lane >> 2, t2 = (lane & 3) * 2;
#pragma unroll
    for (int mi = 0; mi < 4; mi++) {
        int mrow = m0 + wm * 64 + mi * 16 + g;
#pragma unroll
        for (int ni = 0; ni < 4; ni++) {
            int col = n0 + wn * 32 + ni * 8 + t2;
            float b0v = bias[col], b1v = bias[col + 1];
            float2 v0 = { acc[mi][ni][0] + b0v, acc[mi][ni][1] + b1v };
            float2 v1 = { acc[mi][ni][2] + b0v, acc[mi][ni][3] + b1v };
            *(float2*)&C[(size_t)mrow * Ncols + col] = v0;
            *(float2*)&C[(size_t)(mrow + 8) * Ncols + col] = v1;
        }
    }
}

// ---------------------------------------------------------------------------
// grid barrier (co-resident 128 CTAs; monotonic gen -> replay safe)
// ---------------------------------------------------------------------------
__device__ __forceinline__ void grid_barrier(unsigned expected) {
    __syncthreads();
    if (threadIdx.x == 0) {
        __threadfence();
        unsigned gen = *(volatile unsigned*)&g_bar_gen;
        unsigned a = atomicAdd(&g_bar_count, 1);
        if (a == expected - 1) {
            g_bar_count = 0;
            __threadfence();
            atomicAdd(&g_bar_gen, 1);
        } else {
            while (*(volatile unsigned*)&g_bar_gen == gen) { }
        }
        __threadfence();
    }
    __syncthreads();
}

// ---------------------------------------------------------------------------
// persistent fp32 LSTM recurrence (validated R2/R3): 1 launch per layer
// ---------------------------------------------------------------------------
__global__ void __launch_bounds__(256, 1)
lstm_persistent_kernel(const float* __restrict__ state,
                       const float* __restrict__ Wh,
                       const float* __restrict__ pre,
                       float* __restrict__ hseq,
                       float* __restrict__ cfin,
                       float* __restrict__ hfin) {
    __shared__ float As[2][16][32];
    __shared__ float Bs[2][16][64];
    int tid = threadIdx.x;
    int kg = tid >> 7, lt = tid & 127;
    int mt0 = (blockIdx.x & 63) << 4;
    int r0 = (blockIdx.x >> 6) << 5;
    int rg = lt >> 4, cg = lt & 15;
    int m = mt0 + cg;
    int a_row = lt >> 2, a_k = (lt & 3) << 2;
    int b_k = lt >> 3, b_q = lt & 7;

    float c_reg[4];
#pragma unroll
    for (int i = 0; i < 4; i++)
        c_reg[i] = state[(size_t)(r0 + rg * 4 + i) * (2 * MM) + m];

    int kbase = kg << 9;
    float* red = &Bs[0][0][0];

    for (int t = 0; t < TT; t++) {
        const float* hsrc;
        size_t hstr;
        if (t == 0) { hsrc = state + MM; hstr = 2 * MM; }
        else        { hsrc = g_hbuf[t & 1]; hstr = MM; }
        float acc[4][4] = {};
        for (int k0 = 0; k0 < 512; k0 += 16) {
            float4 av = *(const float4*)&hsrc[(size_t)(r0 + a_row) * hstr +
                                              kbase + k0 + a_k];
            As[kg][a_k + 0][a_row] = av.x;
            As[kg][a_k + 1][a_row] = av.y;
            As[kg][a_k + 2][a_row] = av.z;
            As[kg][a_k + 3][a_row] = av.w;
#pragma unroll
            for (int rep = 0; rep < 2; rep++) {
                int q = b_q + rep * 8;
                int g = q >> 2, j4 = (q & 3) << 2;
                float4 bv = *(const float4*)&Wh[(size_t)(kbase + k0 + b_k) * G4 +
                                                g * MM + mt0 + j4];
                Bs[kg][b_k][(j4 + 0) * 4 + g] = bv.x;
                Bs[kg][b_k][(j4 + 1) * 4 + g] = bv.y;
                Bs[kg][b_k][(j4 + 2) * 4 + g] = bv.z;
                Bs[kg][b_k][(j4 + 3) * 4 + g] = bv.w;
            }
            __syncthreads();
#pragma unroll
            for (int kk = 0; kk < 16; kk++) {
                float4 a = *(const float4*)&As[kg][kk][rg * 4];
                float4 b = *(const float4*)&Bs[kg][kk][cg * 4];
                acc[0][0] += a.x * b.x; acc[0][1] += a.x * b.y;
                acc[0][2] += a.x * b.z; acc[0][3] += a.x * b.w;
                acc[1][0] += a.y * b.x; acc[1][1] += a.y * b.y;
                acc[1][2] += a.y * b.z; acc[1][3] += a.y * b.w;
                acc[2][0] += a.z * b.x; acc[2][1] += a.z * b.y;
                acc[2][2] += a.z * b.z; acc[2][3] += a.z * b.w;
                acc[3][0] += a.w * b.x; acc[3][1] += a.w * b.y;
                acc[3][2] += a.w * b.z; acc[3][3] += a.w * b.w;
            }
            __syncthreads();
        }
        if (kg == 1) {
#pragma unroll
            for (int i = 0; i < 4; i++)
#pragma unroll
                for (int j = 0; j < 4; j++)
                    red[lt * 16 + i * 4 + j] = acc[i][j];
        }
        __syncthreads();
        if (kg == 0) {
#pragma unroll
            for (int i = 0; i < 4; i++) {
                int b = r0 + rg * 4 + i;
                size_t pb = ((size_t)b * TT + t) * (size_t)G4 + m;
                float zi = acc[i][0] + red[lt * 16 + i * 4 + 0] + pre[pb];
                float zj = acc[i][1] + red[lt * 16 + i * 4 + 1] + pre[pb + MM];
                float zf = acc[i][2] + red[lt * 16 + i * 4 + 2] + pre[pb + 2 * MM];
                float zo = acc[i][3] + red[lt * 16 + i * 4 + 3] + pre[pb + 3 * MM];
                float fg = sigmoidf_(zf + 1.0f);
                float ig = sigmoidf_(zi);
                float og = sigmoidf_(zo);
                float cv = c_reg[i] * fg + ig * tanhf(zj);
                c_reg[i] = cv;
                float hv = tanhf(cv) * og;
                g_hbuf[(t + 1) & 1][(size_t)b * MM + m] = hv;
                hseq[((size_t)b * TT + t) * (size_t)MM + m] = hv;
                if (t == TT - 1) {
                    cfin[(size_t)b * MM + m] = cv;
                    hfin[(size_t)b * MM + m] = hv;
                }
            }
        }
        grid_barrier(gridDim.x);
    }
}

__global__ void final_state_kernel(float* __restrict__ out) {
    int i = blockIdx.x * blockDim.x + threadIdx.x;
    if (i < 2 * BB * 2 * MM) {
        int l = i / (BB * 2 * MM);
        int r = i % (BB * 2 * MM);
        int b = r / (2 * MM);
        int mm = r % (2 * MM);
        float v = (mm < MM) ? g_cfin[l * BB * MM + b * MM + mm]
                            : g_hfin[l * BB * MM + b * MM + (mm - MM)];
        out[i] = v;
    }
}

// ---------------------------------------------------------------------------
extern "C" void kernel_launch(void* const* d_in, const int* in_sizes, int n_in,
                              void* d_out, int out_size) {
    const float* x      = (const float*)d_in[0];
    const float* state0 = (const float*)d_in[1];
    const float* state1 = (const float*)d_in[2];
    const float* W0     = (const float*)d_in[3];
    const float* b0     = (const float*)d_in[4];
    const float* W1     = (const float*)d_in[5];
    const float* b1     = (const float*)d_in[6];
    const float* W_out  = (const float*)d_in[7];
    const float* b_out  = (const float*)d_in[8];
    float* out = (float*)d_out;

    float *pre, *hseq, *cfin, *hfin;
    cudaGetSymbolAddress((void**)&pre,  g_pre);
    cudaGetSymbolAddress((void**)&hseq, g_hseq);
    cudaGetSymbolAddress((void**)&cfin, g_cfin);
    cudaGetSymbolAddress((void**)&hfin, g_hfin);
    __nv_bfloat16 *Ahi, *Alo, *Wt0h, *Wt0l, *Wt1h, *Wt1l, *WtOh, *WtOl;
    cudaGetSymbolAddress((void**)&Ahi,  g_Ahi);
    cudaGetSymbolAddress((void**)&Alo,  g_Alo);
    cudaGetSymbolAddress((void**)&Wt0h, g_Wt0hi);
    cudaGetSymbolAddress((void**)&Wt0l, g_Wt0lo);
    cudaGetSymbolAddress((void**)&Wt1h, g_Wt1hi);
    cudaGetSymbolAddress((void**)&Wt1l, g_Wt1lo);
    cudaGetSymbolAddress((void**)&WtOh, g_WtOhi);
    cudaGetSymbolAddress((void**)&WtOl, g_WtOlo);

    cudaFuncSetAttribute(gemmT_kernel,
                         cudaFuncAttributeMaxDynamicSharedMemorySize, GT_SMEM);

    // weight preps
    transpose_split_kernel<<<dim3(G4 / 32, VV / 32), 256>>>(W0, G4, Wt0h, Wt0l, VV, G4);
    transpose_split_kernel<<<dim3(G4 / 32, MM / 32), 256>>>(W1, G4, Wt1h, Wt1l, MM, G4);
    transpose_split_kernel<<<dim3(VV / 32, MM / 32), 256>>>(W_out, VV, WtOh, WtOl, MM, VV);

    // pre0 = x @ W0x + b0
    size_t nx = (size_t)BB * TT * VV;
    split_kernel<<<(unsigned)((nx + 255) / 256), 256>>>(x, Ahi, Alo, nx);
    gemmT_kernel<<<dim3(G4 / 128, (BB * TT) / 128), 256, GT_SMEM>>>(
        Ahi, Alo, Wt0h, Wt0l, b0, pre, VV, G4);

    // layer 0
    lstm_persistent_kernel<<<128, 256>>>(
        state0, W0 + (size_t)VV * G4, pre, hseq, cfin, hfin);

    // pre1 = h0_seq @ W1x + b1
    size_t nh = (size_t)BB * TT * MM;
    split_kernel<<<(unsigned)((nh + 255) / 256), 256>>>(hseq, Ahi, Alo, nh);
    gemmT_kernel<<<dim3(G4 / 128, (BB * TT) / 128), 256, GT_SMEM>>>(
        Ahi, Alo, Wt1h, Wt1l, b1, pre, MM, G4);

    // layer 1
    lstm_persistent_kernel<<<128, 256>>>(
        state1, W1 + (size_t)MM * G4, pre, hseq,
        cfin + BB * MM, hfin + BB * MM);

    // outputs = h1_seq @ W_out + b_out
    split_kernel<<<(unsigned)((nh + 255) / 256), 256>>>(hseq, Ahi, Alo, nh);
    gemmT_kernel<<<dim3(VV / 128, (BB * TT) / 128), 256, GT_SMEM>>>(
        Ahi, Alo, WtOh, WtOl, b_out, out, MM, VV);

    final_state_kernel<<<(2 * BB * 2 * MM + 255) / 256, 256>>>(
        out + (size_t)BB * TT * VV);
}

// round 11
// speedup vs baseline: 2.6157x; 2.2890x over previous
#include <cuda_runtime.h>
#include <cuda_bf16.h>
#include <math.h>
#include <stdint.h>

#define BB 64
#define TT 512
#define VV 256
#define MM 1024
#define G4 4096

// ---- static device scratch (no cudaMalloc allowed) ----
__device__ float g_pre[(size_t)BB * TT * G4];    // 512 MB pre-activations
__device__ float g_cfin[2 * BB * MM];
__device__ float g_hfin[2 * BB * MM];
__device__ unsigned g_bar_count;
__device__ unsigned g_bar_gen;
// split-bf16 activation sequence (x splits, then h0 splits, then h1 splits)
__device__ __nv_bfloat16 g_Ahi[(size_t)BB * TT * MM];
__device__ __nv_bfloat16 g_Alo[(size_t)BB * TT * MM];
// initial-h split buffers (per current layer)
__device__ __nv_bfloat16 g_h0h[BB * MM], g_h0l[BB * MM];
// transposed split weights
__device__ __nv_bfloat16 g_Wt0hi[G4 * VV], g_Wt0lo[G4 * VV];          // W0 x-part^T
__device__ __nv_bfloat16 g_Wt1hi[(size_t)G4 * MM], g_Wt1lo[(size_t)G4 * MM];
__device__ __nv_bfloat16 g_WtOhi[VV * MM], g_WtOlo[VV * MM];
__device__ __nv_bfloat16 g_Wh0hi[(size_t)G4 * MM], g_Wh0lo[(size_t)G4 * MM];
__device__ __nv_bfloat16 g_Wh1hi[(size_t)G4 * MM], g_Wh1lo[(size_t)G4 * MM];

__device__ __forceinline__ float sigmoidf_(float x) {
    return 1.0f / (1.0f + __expf(-x));
}

__device__ __forceinline__ uint32_t smem_u32(const void* p) {
    uint32_t a;
    asm("{ .reg .u64 t; cvta.to.shared.u64 t, %1; cvt.u32.u64 %0, t; }"
        : "=r"(a) : "l"(p));
    return a;
}

// ---------------- prep kernels ----------------
__global__ void split_kernel(const float* __restrict__ in,
                             __nv_bfloat16* __restrict__ hi,
                             __nv_bfloat16* __restrict__ lo, size_t n) {
    size_t i = (size_t)blockIdx.x * blockDim.x + threadIdx.x;
    if (i < n) {
        float v = in[i];
        __nv_bfloat16 h = __float2bfloat16_rn(v);
        hi[i] = h;
        lo[i] = __float2bfloat16_rn(v - __bfloat162float(h));
    }
}

// split the h half of state[:, MM:2MM] into contiguous [B][MM] hi/lo
__global__ void split_state_h(const float* __restrict__ state,
                              __nv_bfloat16* __restrict__ hh,
                              __nv_bfloat16* __restrict__ hl) {
    int i = blockIdx.x * blockDim.x + threadIdx.x;
    if (i < BB * MM) {
        int b = i >> 10, m = i & 1023;
        float v = state[(size_t)b * (2 * MM) + MM + m];
        __nv_bfloat16 h = __float2bfloat16_rn(v);
        hh[i] = h;
        hl[i] = __float2bfloat16_rn(v - __bfloat162float(h));
    }
}

// W[k][ldin] (first K rows, N cols) -> T[n][K] hi/lo
__global__ void transpose_split_kernel(const float* __restrict__ W, int ldin,
                                       __nv_bfloat16* __restrict__ Thi,
                                       __nv_bfloat16* __restrict__ Tlo,
                                       int K, int N) {
    __shared__ float tile[32][33];
    int k0 = blockIdx.y * 32, n0 = blockIdx.x * 32;
    int tx = threadIdx.x & 31, ty = threadIdx.x >> 5;
    for (int i = 0; i < 32; i += 8)
        tile[ty + i][tx] = W[(size_t)(k0 + ty + i) * ldin + n0 + tx];
    __syncthreads();
    for (int i = 0; i < 32; i += 8) {
        int n = n0 + ty + i, k = k0 + tx;
        float v = tile[tx][ty + i];
        __nv_bfloat16 h = __float2bfloat16_rn(v);
        Thi[(size_t)n * K + k] = h;
        Tlo[(size_t)n * K + k] = __float2bfloat16_rn(v - __bfloat162float(h));
    }
}

__device__ __forceinline__ void mma_bf16(float* c, const uint32_t* a,
                                         uint32_t b0, uint32_t b1) {
    asm volatile(
        "mma.sync.aligned.m16n8k16.row.col.f32.bf16.bf16.f32 "
        "{%0,%1,%2,%3}, {%4,%5,%6,%7}, {%8,%9}, {%0,%1,%2,%3};"
        : "+f"(c[0]), "+f"(c[1]), "+f"(c[2]), "+f"(c[3])
        : "r"(a[0]), "r"(a[1]), "r"(a[2]), "r"(a[3]), "r"(b0), "r"(b1));
}

// ---------------------------------------------------------------------------
// mma.sync split-bf16 GEMM (validated R10):
// C[M][N] = A[m][K] x (B[n][K])^T + bias.  CTA 128x128, 8 warps, BK=32.
// ---------------------------------------------------------------------------
#define LDS 40
#define TILE_E (128 * LDS)
#define GT_SMEM (2 * 4 * TILE_E * 2)

__device__ __forceinline__ void issue_chunk(
    __nv_bfloat16* st,
    const __nv_bfloat16* Ahi, const __nv_bfloat16* Alo,
    const __nv_bfloat16* Bhi, const __nv_bfloat16* Blo,
    int m0, int n0, int Ktot, int k0, int tid) {
    const __nv_bfloat16* srcs[4] = {Ahi, Alo, Bhi, Blo};
#pragma unroll
    for (int t = 0; t < 4; t++) {
        int rbase = (t < 2) ? m0 : n0;
        const __nv_bfloat16* gp = srcs[t];
#pragma unroll
        for (int i = 0; i < 2; i++) {
            int u = i * 256 + tid;
            int row = u >> 2;
            int koff = (u & 3) * 8;
            uint32_t d = smem_u32(st + t * TILE_E + row * LDS + koff);
            const void* s = gp + (size_t)(rbase + row) * Ktot + k0 + koff;
            asm volatile("cp.async.ca.shared.global [%0], [%1], 16;"
                         :: "r"(d), "l"(s) : "memory");
        }
    }
    asm volatile("cp.async.commit_group;" ::: "memory");
}

__global__ void __launch_bounds__(256, 1)
gemmT_kernel(const __nv_bfloat16* __restrict__ Ahi, const __nv_bfloat16* __restrict__ Alo,
             const __nv_bfloat16* __restrict__ Bhi, const __nv_bfloat16* __restrict__ Blo,
             const float* __restrict__ bias, float* __restrict__ C,
             int Ktot, int Ncols) {
    extern __shared__ __nv_bfloat16 sm[];
    int tid = threadIdx.x, warp = tid >> 5, lane = tid & 31;
    int m0 = blockIdx.y << 7, n0 = blockIdx.x << 7;
    int wm = warp >> 2, wn = warp & 3;
    uint32_t sb = smem_u32(sm);

    float acc[4][4][4];
#pragma unroll
    for (int i = 0; i < 4; i++)
#pragma unroll
        for (int j = 0; j < 4; j++)
#pragma unroll
            for (int q = 0; q < 4; q++) acc[i][j][q] = 0.0f;

    int q4 = lane >> 3, r8 = lane & 7;
    int aro = (q4 & 1) * 8 + r8;
    int aco = (q4 >> 1) * 8;
    int bj = (lane & 15) >> 3;
    int bro = lane & 7;

    int nchunk = Ktot >> 5;
    issue_chunk(sm, Ahi, Alo, Bhi, Blo, m0, n0, Ktot, 0, tid);

    for (int ch = 0; ch < nchunk; ch++) {
        if (ch + 1 < nchunk) {
            issue_chunk(sm + ((ch + 1) & 1) * 4 * TILE_E,
                        Ahi, Alo, Bhi, Blo, m0, n0, Ktot, (ch + 1) << 5, tid);
            asm volatile("cp.async.wait_group 1;" ::: "memory");
        } else {
            asm volatile("cp.async.wait_group 0;" ::: "memory");
        }
        __syncthreads();

        uint32_t stb = sb + (uint32_t)((ch & 1) * 4 * TILE_E * 2);
#pragma unroll
        for (int s = 0; s < 2; s++) {
            uint32_t ah[4][4], al[4][4], bh[4][2], bl[4][2];
#pragma unroll
            for (int mi = 0; mi < 4; mi++) {
                uint32_t ad = stb +
                    (uint32_t)(((wm * 64 + mi * 16 + aro) * LDS + s * 16 + aco) * 2);
                asm volatile(
                    "ldmatrix.sync.aligned.m8n8.x4.shared.b16 {%0,%1,%2,%3}, [%4];"
                    : "=r"(ah[mi][0]), "=r"(ah[mi][1]), "=r"(ah[mi][2]), "=r"(ah[mi][3])
                    : "r"(ad));
                asm volatile(
                    "ldmatrix.sync.aligned.m8n8.x4.shared.b16 {%0,%1,%2,%3}, [%4];"
                    : "=r"(al[mi][0]), "=r"(al[mi][1]), "=r"(al[mi][2]), "=r"(al[mi][3])
                    : "r"(ad + TILE_E * 2));
            }
#pragma unroll
            for (int ni = 0; ni < 4; ni++) {
                uint32_t bd = stb + (uint32_t)((2 * TILE_E +
                    (wn * 32 + ni * 8 + bro) * LDS + s * 16 + bj * 8) * 2);
                asm volatile(
                    "ldmatrix.sync.aligned.m8n8.x2.shared.b16 {%0,%1}, [%2];"
                    : "=r"(bh[ni][0]), "=r"(bh[ni][1]) : "r"(bd));
                asm volatile(
                    "ldmatrix.sync.aligned.m8n8.x2.shared.b16 {%0,%1}, [%2];"
                    : "=r"(bl[ni][0]), "=r"(bl[ni][1]) : "r"(bd + TILE_E * 2));
            }
#pragma unroll
            for (int mi = 0; mi < 4; mi++)
#pragma unroll
                for (int ni = 0; ni < 4; ni++) {
                    mma_bf16(acc[mi][ni], ah[mi], bh[ni][0], bh[ni][1]);
                    mma_bf16(acc[mi][ni], ah[mi], bl[ni][0], bl[ni][1]);
                    mma_bf16(acc[mi][ni], al[mi], bh[ni][0], bh[ni][1]);
                }
        }
        __syncthreads();
    }

    int g = lane >> 2, t2 = (lane & 3) * 2;
#pragma unroll
    for (int mi = 0; mi < 4; mi++) {
        int mrow = m0 + wm * 64 + mi * 16 + g;
#pragma unroll
        for (int ni = 0; ni < 4; ni++) {
            int col = n0 + wn * 32 + ni * 8 + t2;
            float b0v = bias[col], b1v = bias[col + 1];
            float2 v0 = { acc[mi][ni][0] + b0v, acc[mi][ni][1] + b1v };
            float2 v1 = { acc[mi][ni][2] + b0v, acc[mi][ni][3] + b1v };
            *(float2*)&C[(size_t)mrow * Ncols + col] = v0;
            *(float2*)&C[(size_t)(mrow + 8) * Ncols + col] = v1;
        }
    }
}

// ---------------------------------------------------------------------------
// grid barrier (co-resident CTAs; monotonic gen -> replay safe)
// ---------------------------------------------------------------------------
__device__ __forceinline__ void grid_barrier(unsigned expected) {
    __syncthreads();
    if (threadIdx.x == 0) {
        __threadfence();
        unsigned gen = *(volatile unsigned*)&g_bar_gen;
        unsigned a = atomicAdd(&g_bar_count, 1);
        if (a == expected - 1) {
            g_bar_count = 0;
            __threadfence();
            atomicAdd(&g_bar_gen, 1);
        } else {
            while (*(volatile unsigned*)&g_bar_gen == gen) { }
        }
        __threadfence();
    }
    __syncthreads();
}

// ---------------------------------------------------------------------------
// Tensorized persistent LSTM recurrence. 128 CTAs x 256 thr, one launch/layer.
// CTA: mem slice of 8 x 4 gates (N=32 z-cols, cc = g*8+j), M=64 batch, K=1024.
// 8 warps = 4(M) x 2(N), warp tile 16x16. BK=32 double-buffered cp.async.
// 3-pass split-bf16 mma. z combined via smem; c in regs; h written hi/lo
// straight into the sequence split buffers (also next step's A operand).
// ---------------------------------------------------------------------------
#define RK_A_E   2560               // 64 rows * 40
#define RK_B_E   1280               // 32 rows * 40
#define RK_STG_E (2 * RK_A_E + 2 * RK_B_E)   // 7680 elems per stage
#define RK_SMEM  (2 * RK_STG_E * 2 + 64 * 33 * 4)

__device__ __forceinline__ void rk_load_tile(
    uint32_t sb, int stg,
    const __nv_bfloat16* abh, const __nv_bfloat16* abl, size_t rstr,
    const __nv_bfloat16* Whh, const __nv_bfloat16* Whl,
    int mt0, int kt, int tid) {
    int row = tid >> 2;                 // 0..63
    int seg = (tid & 3) * 8;            // k offset
    uint32_t base = sb + (uint32_t)(stg * RK_STG_E * 2);
    int kk = kt * 32 + seg;
    // A hi
    asm volatile("cp.async.ca.shared.global [%0], [%1], 16;"
        :: "r"(base + (uint32_t)((row * LDS + seg) * 2)),
           "l"(abh + (size_t)row * rstr + kk) : "memory");
    // A lo
    asm volatile("cp.async.ca.shared.global [%0], [%1], 16;"
        :: "r"(base + (uint32_t)((RK_A_E + row * LDS + seg) * 2)),
           "l"(abl + (size_t)row * rstr + kk) : "memory");
    // B hi / lo (tid<128 -> hi, else lo)
    int cc = (tid & 127) >> 2;          // 0..31
    int n = (cc >> 3) * MM + mt0 + (cc & 7);
    const __nv_bfloat16* wsrc = (tid < 128) ? Whh : Whl;
    uint32_t boff = (uint32_t)((2 * RK_A_E + ((tid < 128) ? 0 : RK_B_E) +
                                cc * LDS + seg) * 2);
    asm volatile("cp.async.ca.shared.global [%0], [%1], 16;"
        :: "r"(base + boff), "l"(wsrc + (size_t)n * MM + kk) : "memory");
    asm volatile("cp.async.commit_group;" ::: "memory");
}

__global__ void __launch_bounds__(256, 1)
lstm_mma_persistent(const float* __restrict__ state,       // [B,2MM] (c|h)
                    const __nv_bfloat16* __restrict__ Whh, // [G4][MM]
                    const __nv_bfloat16* __restrict__ Whl,
                    const __nv_bfloat16* __restrict__ h0h, // [B][MM]
                    const __nv_bfloat16* __restrict__ h0l,
                    const float* __restrict__ pre,         // [B][T][G4]
                    __nv_bfloat16* __restrict__ hsh,       // [B][T][MM]
                    __nv_bfloat16* __restrict__ hsl,
                    float* __restrict__ cfin, float* __restrict__ hfin) {
    extern __shared__ __nv_bfloat16 smraw[];
    float* zex = (float*)(smraw + 2 * RK_STG_E);
    uint32_t sb = smem_u32(smraw);

    int tid = threadIdx.x, lane = tid & 31, warp = tid >> 5;
    int wm = warp >> 1, wn = warp & 1;
    int mt0 = blockIdx.x * 8;

    // epilogue ownership: pair p -> (b = tid/8 + p*32, j = tid&7)
    int be = tid >> 3, je = tid & 7;
    float c0 = state[(size_t)be * (2 * MM) + mt0 + je];
    float c1 = state[(size_t)(be + 32) * (2 * MM) + mt0 + je];

    // ldmatrix lane components
    int aro = lane & 15, aco = (lane >> 4) * 8;
    int bro = lane & 7, bj = (lane & 15) >> 3;

    for (int t = 0; t < TT; t++) {
        const __nv_bfloat16 *abh, *abl;
        size_t rstr;
        if (t == 0) { abh = h0h; abl = h0l; rstr = MM; }
        else {
            abh = hsh + (size_t)(t - 1) * MM;
            abl = hsl + (size_t)(t - 1) * MM;
            rstr = (size_t)TT * MM;
        }

        // prefetch pre values (8 independent LDGs, live across mainloop)
        float pv[8];
#pragma unroll
        for (int g = 0; g < 4; g++) {
            pv[g]     = pre[((size_t)be * TT + t) * G4 + g * MM + mt0 + je];
            pv[4 + g] = pre[((size_t)(be + 32) * TT + t) * G4 + g * MM + mt0 + je];
        }

        float acc[2][4] = {{0, 0, 0, 0}, {0, 0, 0, 0}};

        rk_load_tile(sb, 0, abh, abl, rstr, Whh, Whl, mt0, 0, tid);
        for (int kt = 0; kt < 32; kt++) {
            if (kt + 1 < 32) {
                rk_load_tile(sb, (kt + 1) & 1, abh, abl, rstr, Whh, Whl,
                             mt0, kt + 1, tid);
                asm volatile("cp.async.wait_group 1;" ::: "memory");
            } else {
                asm volatile("cp.async.wait_group 0;" ::: "memory");
            }
            __syncthreads();

            uint32_t stb = sb + (uint32_t)(((kt & 1) * RK_STG_E) * 2);
#pragma unroll
            for (int s = 0; s < 2; s++) {
                uint32_t ah[4], al4[4];
                uint32_t ad = stb + (uint32_t)(((wm * 16 + aro) * LDS +
                                               s * 16 + aco) * 2);
                asm volatile(
                    "ldmatrix.sync.aligned.m8n8.x4.shared.b16 {%0,%1,%2,%3}, [%4];"
                    : "=r"(ah[0]), "=r"(ah[1]), "=r"(ah[2]), "=r"(ah[3]) : "r"(ad));
                asm volatile(
                    "ldmatrix.sync.aligned.m8n8.x4.shared.b16 {%0,%1,%2,%3}, [%4];"
                    : "=r"(al4[0]), "=r"(al4[1]), "=r"(al4[2]), "=r"(al4[3])
                    : "r"(ad + RK_A_E * 2));
#pragma unroll
                for (int ni = 0; ni < 2; ni++) {
                    uint32_t bh0, bh1, bl0, bl1;
                    uint32_t bd = stb + (uint32_t)((2 * RK_A_E +
                        (wn * 16 + ni * 8 + bro) * LDS + s * 16 + bj * 8) * 2);
                    asm volatile(
                        "ldmatrix.sync.aligned.m8n8.x2.shared.b16 {%0,%1}, [%2];"
                        : "=r"(bh0), "=r"(bh1) : "r"(bd));
                    asm volatile(
                        "ldmatrix.sync.aligned.m8n8.x2.shared.b16 {%0,%1}, [%2];"
                        : "=r"(bl0), "=r"(bl1) : "r"(bd + RK_B_E * 2));
                    mma_bf16(acc[ni], ah, bh0, bh1);
                    mma_bf16(acc[ni], ah, bl0, bl1);
                    mma_bf16(acc[ni], al4, bh0, bh1);
                }
            }
            __syncthreads();
        }

        // z exchange through smem
#pragma unroll
        for (int ni = 0; ni < 2; ni++) {
            int r = wm * 16 + (lane >> 2);
            int c = wn * 16 + ni * 8 + (lane & 3) * 2;
            zex[r * 33 + c]           = acc[ni][0];
            zex[r * 33 + c + 1]       = acc[ni][1];
            zex[(r + 8) * 33 + c]     = acc[ni][2];
            zex[(r + 8) * 33 + c + 1] = acc[ni][3];
        }
        __syncthreads();

        // gates for 2 (b, m) pairs
#pragma unroll
        for (int p = 0; p < 2; p++) {
            int b = be + p * 32;
            float zi = zex[b * 33 +      je] + pv[p * 4 + 0];
            float zj = zex[b * 33 +  8 + je] + pv[p * 4 + 1];
            float zf = zex[b * 33 + 16 + je] + pv[p * 4 + 2];
            float zo = zex[b * 33 + 24 + je] + pv[p * 4 + 3];
            float fg = sigmoidf_(zf + 1.0f);   // FORGET_BIAS
            float ig = sigmoidf_(zi);
            float og = sigmoidf_(zo);
            float cv = (p ? c1 : c0) * fg + ig * tanhf(zj);
            if (p) c1 = cv; else c0 = cv;
            float hv = tanhf(cv) * og;
            size_t ha = ((size_t)b * TT + t) * MM + mt0 + je;
            __nv_bfloat16 hh = __float2bfloat16_rn(hv);
            hsh[ha] = hh;
            hsl[ha] = __float2bfloat16_rn(hv - __bfloat162float(hh));
            if (t == TT - 1) {
                cfin[(size_t)b * MM + mt0 + je] = cv;
                hfin[(size_t)b * MM + mt0 + je] = hv;
            }
        }
        grid_barrier(gridDim.x);
    }
}

// ---------------------------------------------------------------------------
// final_state: out layout [2][BB][2*MM], row = concat(c, h)
// ---------------------------------------------------------------------------
__global__ void final_state_kernel(float* __restrict__ out) {
    int i = blockIdx.x * blockDim.x + threadIdx.x;
    if (i < 2 * BB * 2 * MM) {
        int l = i / (BB * 2 * MM);
        int r = i % (BB * 2 * MM);
        int b = r / (2 * MM);
        int mm = r % (2 * MM);
        float v = (mm < MM) ? g_cfin[l * BB * MM + b * MM + mm]
                            : g_hfin[l * BB * MM + b * MM + (mm - MM)];
        out[i] = v;
    }
}

// ---------------------------------------------------------------------------
extern "C" void kernel_launch(void* const* d_in, const int* in_sizes, int n_in,
                              void* d_out, int out_size) {
    const float* x      = (const float*)d_in[0];
    const float* state0 = (const float*)d_in[1];
    const float* state1 = (const float*)d_in[2];
    const float* W0     = (const float*)d_in[3];
    const float* b0     = (const float*)d_in[4];
    const float* W1     = (const float*)d_in[5];
    const float* b1     = (const float*)d_in[6];
    const float* W_out  = (const float*)d_in[7];
    const float* b_out  = (const float*)d_in[8];
    float* out = (float*)d_out;

    float *pre, *cfin, *hfin;
    cudaGetSymbolAddress((void**)&pre,  g_pre);
    cudaGetSymbolAddress((void**)&cfin, g_cfin);
    cudaGetSymbolAddress((void**)&hfin, g_hfin);
    __nv_bfloat16 *Ahi, *Alo, *h0h, *h0l;
    __nv_bfloat16 *Wt0h, *Wt0l, *Wt1h, *Wt1l, *WtOh, *WtOl;
    __nv_bfloat16 *Wh0h, *Wh0l, *Wh1h, *Wh1l;
    cudaGetSymbolAddress((void**)&Ahi,  g_Ahi);
    cudaGetSymbolAddress((void**)&Alo,  g_Alo);
    cudaGetSymbolAddress((void**)&h0h,  g_h0h);
    cudaGetSymbolAddress((void**)&h0l,  g_h0l);
    cudaGetSymbolAddress((void**)&Wt0h, g_Wt0hi);
    cudaGetSymbolAddress((void**)&Wt0l, g_Wt0lo);
    cudaGetSymbolAddress((void**)&Wt1h, g_Wt1hi);
    cudaGetSymbolAddress((void**)&Wt1l, g_Wt1lo);
    cudaGetSymbolAddress((void**)&WtOh, g_WtOhi);
    cudaGetSymbolAddress((void**)&WtOl, g_WtOlo);
    cudaGetSymbolAddress((void**)&Wh0h, g_Wh0hi);
    cudaGetSymbolAddress((void**)&Wh0l, g_Wh0lo);
    cudaGetSymbolAddress((void**)&Wh1h, g_Wh1hi);
    cudaGetSymbolAddress((void**)&Wh1l, g_Wh1lo);

    cudaFuncSetAttribute(gemmT_kernel,
                         cudaFuncAttributeMaxDynamicSharedMemorySize, GT_SMEM);
    cudaFuncSetAttribute(lstm_mma_persistent,
                         cudaFuncAttributeMaxDynamicSharedMemorySize, RK_SMEM);

    // weight preps (transpose + split)
    transpose_split_kernel<<<dim3(G4 / 32, VV / 32), 256>>>(W0, G4, Wt0h, Wt0l, VV, G4);
    transpose_split_kernel<<<dim3(G4 / 32, MM / 32), 256>>>(W1, G4, Wt1h, Wt1l, MM, G4);
    transpose_split_kernel<<<dim3(VV / 32, MM / 32), 256>>>(W_out, VV, WtOh, WtOl, MM, VV);
    transpose_split_kernel<<<dim3(G4 / 32, MM / 32), 256>>>(
        W0 + (size_t)VV * G4, G4, Wh0h, Wh0l, MM, G4);
    transpose_split_kernel<<<dim3(G4 / 32, MM / 32), 256>>>(
        W1 + (size_t)MM * G4, G4, Wh1h, Wh1l, MM, G4);

    // pre0 = x @ W0x + b0
    size_t nx = (size_t)BB * TT * VV;
    split_kernel<<<(unsigned)((nx + 255) / 256), 256>>>(x, Ahi, Alo, nx);
    gemmT_kernel<<<dim3(G4 / 128, (BB * TT) / 128), 256, GT_SMEM>>>(
        Ahi, Alo, Wt0h, Wt0l, b0, pre, VV, G4);

    // layer 0 recurrence (writes h0 splits into Ahi/Alo)
    split_state_h<<<(BB * MM + 255) / 256, 256>>>(state0, h0h, h0l);
    lstm_mma_persistent<<<128, 256, RK_SMEM>>>(
        state0, Wh0h, Wh0l, h0h, h0l, pre, Ahi, Alo, cfin, hfin);

    // pre1 = h0_seq @ W1x + b1 (A splits already in Ahi/Alo)
    gemmT_kernel<<<dim3(G4 / 128, (BB * TT) / 128), 256, GT_SMEM>>>(
        Ahi, Alo, Wt1h, Wt1l, b1, pre, MM, G4);

    // layer 1 recurrence (overwrites Ahi/Alo with h1 splits)
    split_state_h<<<(BB * MM + 255) / 256, 256>>>(state1, h0h, h0l);
    lstm_mma_persistent<<<128, 256, RK_SMEM>>>(
        state1, Wh1h, Wh1l, h0h, h0l, pre, Ahi, Alo,
        cfin + BB * MM, hfin + BB * MM);

    // outputs = h1_seq @ W_out + b_out
    gemmT_kernel<<<dim3(VV / 128, (BB * TT) / 128), 256, GT_SMEM>>>(
        Ahi, Alo, WtOh, WtOl, b_out, out, MM, VV);

    final_state_kernel<<<(2 * BB * 2 * MM + 255) / 256, 256>>>(
        out + (size_t)BB * TT * VV);
}

// round 12
// speedup vs baseline: 3.4344x; 1.3130x over previous
#include <cuda_runtime.h>
#include <cuda_bf16.h>
#include <math.h>
#include <stdint.h>

#define BB 64
#define TT 512
#define VV 256
#define MM 1024
#define G4 4096

// ---- static device scratch (no cudaMalloc allowed) ----
__device__ float g_pre[(size_t)BB * TT * G4];    // 512 MB pre-activations
__device__ float g_cfin[2 * BB * MM];
__device__ float g_hfin[2 * BB * MM];
__device__ unsigned g_bar_count;
__device__ unsigned g_bar_gen;
// split-bf16 activation sequence (x splits, then h0 splits, then h1 splits)
__device__ __nv_bfloat16 g_Ahi[(size_t)BB * TT * MM];
__device__ __nv_bfloat16 g_Alo[(size_t)BB * TT * MM];
__device__ __nv_bfloat16 g_h0h[BB * MM], g_h0l[BB * MM];
// transposed split weights
__device__ __nv_bfloat16 g_Wt0hi[G4 * VV], g_Wt0lo[G4 * VV];
__device__ __nv_bfloat16 g_Wt1hi[(size_t)G4 * MM], g_Wt1lo[(size_t)G4 * MM];
__device__ __nv_bfloat16 g_WtOhi[VV * MM], g_WtOlo[VV * MM];
__device__ __nv_bfloat16 g_Wh0hi[(size_t)G4 * MM], g_Wh0lo[(size_t)G4 * MM];
__device__ __nv_bfloat16 g_Wh1hi[(size_t)G4 * MM], g_Wh1lo[(size_t)G4 * MM];

__device__ __forceinline__ float sigmoidf_(float x) {
    return 1.0f / (1.0f + __expf(-x));
}

__device__ __forceinline__ uint32_t smem_u32(const void* p) {
    uint32_t a;
    asm("{ .reg .u64 t; cvta.to.shared.u64 t, %1; cvt.u32.u64 %0, t; }"
        : "=r"(a) : "l"(p));
    return a;
}

// ---------------- prep kernels ----------------
__global__ void split_kernel(const float* __restrict__ in,
                             __nv_bfloat16* __restrict__ hi,
                             __nv_bfloat16* __restrict__ lo, size_t n) {
    size_t i = (size_t)blockIdx.x * blockDim.x + threadIdx.x;
    if (i < n) {
        float v = in[i];
        __nv_bfloat16 h = __float2bfloat16_rn(v);
        hi[i] = h;
        lo[i] = __float2bfloat16_rn(v - __bfloat162float(h));
    }
}

__global__ void split_state_h(const float* __restrict__ state,
                              __nv_bfloat16* __restrict__ hh,
                              __nv_bfloat16* __restrict__ hl) {
    int i = blockIdx.x * blockDim.x + threadIdx.x;
    if (i < BB * MM) {
        int b = i >> 10, m = i & 1023;
        float v = state[(size_t)b * (2 * MM) + MM + m];
        __nv_bfloat16 h = __float2bfloat16_rn(v);
        hh[i] = h;
        hl[i] = __float2bfloat16_rn(v - __bfloat162float(h));
    }
}

// W[k][ldin] (first K rows, N cols) -> T[n][K] hi/lo
__global__ void transpose_split_kernel(const float* __restrict__ W, int ldin,
                                       __nv_bfloat16* __restrict__ Thi,
                                       __nv_bfloat16* __restrict__ Tlo,
                                       int K, int N) {
    __shared__ float tile[32][33];
    int k0 = blockIdx.y * 32, n0 = blockIdx.x * 32;
    int tx = threadIdx.x & 31, ty = threadIdx.x >> 5;
    for (int i = 0; i < 32; i += 8)
        tile[ty + i][tx] = W[(size_t)(k0 + ty + i) * ldin + n0 + tx];
    __syncthreads();
    for (int i = 0; i < 32; i += 8) {
        int n = n0 + ty + i, k = k0 + tx;
        float v = tile[tx][ty + i];
        __nv_bfloat16 h = __float2bfloat16_rn(v);
        Thi[(size_t)n * K + k] = h;
        Tlo[(size_t)n * K + k] = __float2bfloat16_rn(v - __bfloat162float(h));
    }
}

__device__ __forceinline__ void mma_bf16(float* c, const uint32_t* a,
                                         uint32_t b0, uint32_t b1) {
    asm volatile(
        "mma.sync.aligned.m16n8k16.row.col.f32.bf16.bf16.f32 "
        "{%0,%1,%2,%3}, {%4,%5,%6,%7}, {%8,%9}, {%0,%1,%2,%3};"
        : "+f"(c[0]), "+f"(c[1]), "+f"(c[2]), "+f"(c[3])
        : "r"(a[0]), "r"(a[1]), "r"(a[2]), "r"(a[3]), "r"(b0), "r"(b1));
}

// ---------------------------------------------------------------------------
// mma.sync split-bf16 GEMM (validated R10/R11); stride 40 -> 56 (conflict-free)
// ---------------------------------------------------------------------------
#define GLDS 56
#define TILE_E (128 * GLDS)
#define GT_SMEM (2 * 4 * TILE_E * 2)

__device__ __forceinline__ void issue_chunk(
    __nv_bfloat16* st,
    const __nv_bfloat16* Ahi, const __nv_bfloat16* Alo,
    const __nv_bfloat16* Bhi, const __nv_bfloat16* Blo,
    int m0, int n0, int Ktot, int k0, int tid) {
    const __nv_bfloat16* srcs[4] = {Ahi, Alo, Bhi, Blo};
#pragma unroll
    for (int t = 0; t < 4; t++) {
        int rbase = (t < 2) ? m0 : n0;
        const __nv_bfloat16* gp = srcs[t];
#pragma unroll
        for (int i = 0; i < 2; i++) {
            int u = i * 256 + tid;
            int row = u >> 2;
            int koff = (u & 3) * 8;
            uint32_t d = smem_u32(st + t * TILE_E + row * GLDS + koff);
            const void* s = gp + (size_t)(rbase + row) * Ktot + k0 + koff;
            asm volatile("cp.async.ca.shared.global [%0], [%1], 16;"
                         :: "r"(d), "l"(s) : "memory");
        }
    }
    asm volatile("cp.async.commit_group;" ::: "memory");
}

__global__ void __launch_bounds__(256, 1)
gemmT_kernel(const __nv_bfloat16* __restrict__ Ahi, const __nv_bfloat16* __restrict__ Alo,
             const __nv_bfloat16* __restrict__ Bhi, const __nv_bfloat16* __restrict__ Blo,
             const float* __restrict__ bias, float* __restrict__ C,
             int Ktot, int Ncols) {
    extern __shared__ __nv_bfloat16 sm[];
    int tid = threadIdx.x, warp = tid >> 5, lane = tid & 31;
    int m0 = blockIdx.y << 7, n0 = blockIdx.x << 7;
    int wm = warp >> 2, wn = warp & 3;
    uint32_t sb = smem_u32(sm);

    float acc[4][4][4];
#pragma unroll
    for (int i = 0; i < 4; i++)
#pragma unroll
        for (int j = 0; j < 4; j++)
#pragma unroll
            for (int q = 0; q < 4; q++) acc[i][j][q] = 0.0f;

    int q4 = lane >> 3, r8 = lane & 7;
    int aro = (q4 & 1) * 8 + r8;
    int aco = (q4 >> 1) * 8;
    int bj = (lane & 15) >> 3;
    int bro = lane & 7;

    int nchunk = Ktot >> 5;
    issue_chunk(sm, Ahi, Alo, Bhi, Blo, m0, n0, Ktot, 0, tid);

    for (int ch = 0; ch < nchunk; ch++) {
        if (ch + 1 < nchunk) {
            issue_chunk(sm + ((ch + 1) & 1) * 4 * TILE_E,
                        Ahi, Alo, Bhi, Blo, m0, n0, Ktot, (ch + 1) << 5, tid);
            asm volatile("cp.async.wait_group 1;" ::: "memory");
        } else {
            asm volatile("cp.async.wait_group 0;" ::: "memory");
        }
        __syncthreads();

        uint32_t stb = sb + (uint32_t)((ch & 1) * 4 * TILE_E * 2);
#pragma unroll
        for (int s = 0; s < 2; s++) {
            uint32_t ah[4][4], al[4][4], bh[4][2], bl[4][2];
#pragma unroll
            for (int mi = 0; mi < 4; mi++) {
                uint32_t ad = stb +
                    (uint32_t)(((wm * 64 + mi * 16 + aro) * GLDS + s * 16 + aco) * 2);
                asm volatile(
                    "ldmatrix.sync.aligned.m8n8.x4.shared.b16 {%0,%1,%2,%3}, [%4];"
                    : "=r"(ah[mi][0]), "=r"(ah[mi][1]), "=r"(ah[mi][2]), "=r"(ah[mi][3])
                    : "r"(ad));
                asm volatile(
                    "ldmatrix.sync.aligned.m8n8.x4.shared.b16 {%0,%1,%2,%3}, [%4];"
                    : "=r"(al[mi][0]), "=r"(al[mi][1]), "=r"(al[mi][2]), "=r"(al[mi][3])
                    : "r"(ad + TILE_E * 2));
            }
#pragma unroll
            for (int ni = 0; ni < 4; ni++) {
                uint32_t bd = stb + (uint32_t)((2 * TILE_E +
                    (wn * 32 + ni * 8 + bro) * GLDS + s * 16 + bj * 8) * 2);
                asm volatile(
                    "ldmatrix.sync.aligned.m8n8.x2.shared.b16 {%0,%1}, [%2];"
                    : "=r"(bh[ni][0]), "=r"(bh[ni][1]) : "r"(bd));
                asm volatile(
                    "ldmatrix.sync.aligned.m8n8.x2.shared.b16 {%0,%1}, [%2];"
                    : "=r"(bl[ni][0]), "=r"(bl[ni][1]) : "r"(bd + TILE_E * 2));
            }
#pragma unroll
            for (int mi = 0; mi < 4; mi++)
#pragma unroll
                for (int ni = 0; ni < 4; ni++) {
                    mma_bf16(acc[mi][ni], ah[mi], bh[ni][0], bh[ni][1]);
                    mma_bf16(acc[mi][ni], ah[mi], bl[ni][0], bl[ni][1]);
                    mma_bf16(acc[mi][ni], al[mi], bh[ni][0], bh[ni][1]);
                }
        }
        __syncthreads();
    }

    int g = lane >> 2, t2 = (lane & 3) * 2;
#pragma unroll
    for (int mi = 0; mi < 4; mi++) {
        int mrow = m0 + wm * 64 + mi * 16 + g;
#pragma unroll
        for (int ni = 0; ni < 4; ni++) {
            int col = n0 + wn * 32 + ni * 8 + t2;
            float b0v = bias[col], b1v = bias[col + 1];
            float2 v0 = { acc[mi][ni][0] + b0v, acc[mi][ni][1] + b1v };
            float2 v1 = { acc[mi][ni][2] + b0v, acc[mi][ni][3] + b1v };
            *(float2*)&C[(size_t)mrow * Ncols + col] = v0;
            *(float2*)&C[(size_t)(mrow + 8) * Ncols + col] = v1;
        }
    }
}

// ---------------------------------------------------------------------------
// grid barrier
// ---------------------------------------------------------------------------
__device__ __forceinline__ void grid_barrier(unsigned expected) {
    __syncthreads();
    if (threadIdx.x == 0) {
        __threadfence();
        unsigned gen = *(volatile unsigned*)&g_bar_gen;
        unsigned a = atomicAdd(&g_bar_count, 1);
        if (a == expected - 1) {
            g_bar_count = 0;
            __threadfence();
            atomicAdd(&g_bar_gen, 1);
        } else {
            while (*(volatile unsigned*)&g_bar_gen == gen) { }
        }
        __threadfence();
    }
    __syncthreads();
}

// ---------------------------------------------------------------------------
// Tensorized persistent LSTM recurrence v2.
// - Weights persistent in SMEM (132 KB/CTA, loaded once; stride 1032 -> CF)
// - A (h) double-buffered cp.async, 64-k stages, stride 72 (conflict-free)
// - 8 warps = 2(wm) x 2(wn) x 2(kg K-half); warp tile 32x16; zex0/zex1 reduce
// ---------------------------------------------------------------------------
#define RLDS   72
#define RA_E   (64 * RLDS)              // 4608 elems per split tile
#define RSTG_B (2 * RA_E * 2)           // 18432 bytes per stage (hi+lo)
#define ZEX_B  (36864)                  // zex0 offset
#define BW_B   (36864 + 16896)          // weight region offset = 53760
#define BSTR   1032
#define BSPL_B (32 * BSTR * 2)          // 66048 bytes per weight split
#define RK_SMEM (BW_B + 2 * BSPL_B)     // 185856 bytes

__device__ __forceinline__ void rk_load_A(
    uint32_t sb, int stg,
    const __nv_bfloat16* abh, const __nv_bfloat16* abl, size_t rstr,
    int it, int tid) {
    uint32_t base = sb + (uint32_t)(stg * RSTG_B);
    int k0 = it * 64;
#pragma unroll
    for (int i = 0; i < 2; i++) {
        int u = i * 256 + tid;             // 0..511
        int row = u >> 3;                  // 0..63
        int seg = (u & 7) * 8;             // 0..56
        asm volatile("cp.async.ca.shared.global [%0], [%1], 16;"
            :: "r"(base + (uint32_t)((row * RLDS + seg) * 2)),
               "l"(abh + (size_t)row * rstr + k0 + seg) : "memory");
        asm volatile("cp.async.ca.shared.global [%0], [%1], 16;"
            :: "r"(base + (uint32_t)((RA_E + row * RLDS + seg) * 2)),
               "l"(abl + (size_t)row * rstr + k0 + seg) : "memory");
    }
    asm volatile("cp.async.commit_group;" ::: "memory");
}

__global__ void __launch_bounds__(256, 1)
lstm_mma_persistent(const float* __restrict__ state,       // [B,2MM] (c|h)
                    const __nv_bfloat16* __restrict__ Whh, // [G4 rows][MM k]
                    const __nv_bfloat16* __restrict__ Whl,
                    const __nv_bfloat16* __restrict__ h0h, // [B][MM]
                    const __nv_bfloat16* __restrict__ h0l,
                    const float* __restrict__ pre,         // [B][T][G4]
                    __nv_bfloat16* __restrict__ hsh,       // [B][T][MM]
                    __nv_bfloat16* __restrict__ hsl,
                    float* __restrict__ cfin, float* __restrict__ hfin) {
    extern __shared__ uint8_t smraw[];
    uint32_t sb = smem_u32(smraw);
    float* zex0 = (float*)(smraw + ZEX_B);
    float* zex1 = (float*)(smraw + ZEX_B + 8448);

    int tid = threadIdx.x, lane = tid & 31, warp = tid >> 5;
    int wm = warp >> 2, wn = (warp >> 1) & 1, kg = warp & 1;
    int mt0 = blockIdx.x * 8;

    // ---- preload recurrent weights into persistent SMEM (once) ----
    for (int i = tid; i < 4096; i += 256) {        // 16B chunks, hi+lo together
        int cc = i >> 7, ch = i & 127;
        int n = (cc >> 3) * MM + mt0 + (cc & 7);
        uint32_t d = sb + BW_B + (uint32_t)((cc * BSTR + ch * 8) * 2);
        asm volatile("cp.async.ca.shared.global [%0], [%1], 16;"
            :: "r"(d), "l"(Whh + (size_t)n * MM + ch * 8) : "memory");
        asm volatile("cp.async.ca.shared.global [%0], [%1], 16;"
            :: "r"(d + BSPL_B), "l"(Whl + (size_t)n * MM + ch * 8) : "memory");
    }
    asm volatile("cp.async.commit_group;" ::: "memory");
    asm volatile("cp.async.wait_group 0;" ::: "memory");
    __syncthreads();

    // epilogue ownership: (b = tid/8 (+32), j = tid&7)
    int be = tid >> 3, je = tid & 7;
    float c0 = state[(size_t)be * (2 * MM) + mt0 + je];
    float c1 = state[(size_t)(be + 32) * (2 * MM) + mt0 + je];

    int aro = lane & 15, aco = (lane >> 4) * 8;
    int bro = lane & 7, bj = (lane & 15) >> 3;

    for (int t = 0; t < TT; t++) {
        const __nv_bfloat16 *abh, *abl;
        size_t rstr;
        if (t == 0) { abh = h0h; abl = h0l; rstr = MM; }
        else {
            abh = hsh + (size_t)(t - 1) * MM;
            abl = hsl + (size_t)(t - 1) * MM;
            rstr = (size_t)TT * MM;
        }

        float pv[8];
#pragma unroll
        for (int g = 0; g < 4; g++) {
            pv[g]     = pre[((size_t)be * TT + t) * G4 + g * MM + mt0 + je];
            pv[4 + g] = pre[((size_t)(be + 32) * TT + t) * G4 + g * MM + mt0 + je];
        }

        float acc[2][2][4];
#pragma unroll
        for (int mi = 0; mi < 2; mi++)
#pragma unroll
            for (int ni = 0; ni < 2; ni++)
#pragma unroll
                for (int q = 0; q < 4; q++) acc[mi][ni][q] = 0.0f;

        rk_load_A(sb, 0, abh, abl, rstr, 0, tid);
        for (int it = 0; it < 16; it++) {
            if (it + 1 < 16) {
                rk_load_A(sb, (it + 1) & 1, abh, abl, rstr, it + 1, tid);
                asm volatile("cp.async.wait_group 1;" ::: "memory");
            } else {
                asm volatile("cp.async.wait_group 0;" ::: "memory");
            }
            __syncthreads();

            uint32_t stb = sb + (uint32_t)((it & 1) * RSTG_B);
#pragma unroll
            for (int s = 0; s < 2; s++) {
                uint32_t ah[2][4], al[2][4];
#pragma unroll
                for (int mi = 0; mi < 2; mi++) {
                    uint32_t ad = stb + (uint32_t)(((wm * 32 + mi * 16 + aro) * RLDS +
                                                   kg * 32 + s * 16 + aco) * 2);
                    asm volatile(
                        "ldmatrix.sync.aligned.m8n8.x4.shared.b16 {%0,%1,%2,%3}, [%4];"
                        : "=r"(ah[mi][0]), "=r"(ah[mi][1]), "=r"(ah[mi][2]), "=r"(ah[mi][3])
                        : "r"(ad));
                    asm volatile(
                        "ldmatrix.sync.aligned.m8n8.x4.shared.b16 {%0,%1,%2,%3}, [%4];"
                        : "=r"(al[mi][0]), "=r"(al[mi][1]), "=r"(al[mi][2]), "=r"(al[mi][3])
                        : "r"(ad + RA_E * 2));
                }
#pragma unroll
                for (int ni = 0; ni < 2; ni++) {
                    uint32_t bh0, bh1, bl0, bl1;
                    uint32_t bd = sb + BW_B + (uint32_t)((
                        (wn * 16 + ni * 8 + bro) * BSTR +
                        it * 64 + kg * 32 + s * 16 + bj * 8) * 2);
                    asm volatile(
                        "ldmatrix.sync.aligned.m8n8.x2.shared.b16 {%0,%1}, [%2];"
                        : "=r"(bh0), "=r"(bh1) : "r"(bd));
                    asm volatile(
                        "ldmatrix.sync.aligned.m8n8.x2.shared.b16 {%0,%1}, [%2];"
                        : "=r"(bl0), "=r"(bl1) : "r"(bd + BSPL_B));
#pragma unroll
                    for (int mi = 0; mi < 2; mi++) {
                        mma_bf16(acc[mi][ni], ah[mi], bh0, bh1);
                        mma_bf16(acc[mi][ni], ah[mi], bl0, bl1);
                        mma_bf16(acc[mi][ni], al[mi], bh0, bh1);
                    }
                }
            }
            __syncthreads();
        }

        // partial-z exchange (kg halves in separate buffers)
        float* zx = kg ? zex1 : zex0;
#pragma unroll
        for (int mi = 0; mi < 2; mi++)
#pragma unroll
            for (int ni = 0; ni < 2; ni++) {
                int r = wm * 32 + mi * 16 + (lane >> 2);
                int c = wn * 16 + ni * 8 + (lane & 3) * 2;
                zx[r * 33 + c]           = acc[mi][ni][0];
                zx[r * 33 + c + 1]       = acc[mi][ni][1];
                zx[(r + 8) * 33 + c]     = acc[mi][ni][2];
                zx[(r + 8) * 33 + c + 1] = acc[mi][ni][3];
            }
        __syncthreads();

#pragma unroll
        for (int p = 0; p < 2; p++) {
            int b = be + p * 32;
            float zi = zex0[b * 33 +      je] + zex1[b * 33 +      je] + pv[p * 4 + 0];
            float zj = zex0[b * 33 +  8 + je] + zex1[b * 33 +  8 + je] + pv[p * 4 + 1];
            float zf = zex0[b * 33 + 16 + je] + zex1[b * 33 + 16 + je] + pv[p * 4 + 2];
            float zo = zex0[b * 33 + 24 + je] + zex1[b * 33 + 24 + je] + pv[p * 4 + 3];
            float fg = sigmoidf_(zf + 1.0f);   // FORGET_BIAS
            float ig = sigmoidf_(zi);
            float og = sigmoidf_(zo);
            float cv = (p ? c1 : c0) * fg + ig * tanhf(zj);
            if (p) c1 = cv; else c0 = cv;
            float hv = tanhf(cv) * og;
            size_t ha = ((size_t)b * TT + t) * MM + mt0 + je;
            __nv_bfloat16 hh = __float2bfloat16_rn(hv);
            hsh[ha] = hh;
            hsl[ha] = __float2bfloat16_rn(hv - __bfloat162float(hh));
            if (t == TT - 1) {
                cfin[(size_t)b * MM + mt0 + je] = cv;
                hfin[(size_t)b * MM + mt0 + je] = hv;
            }
        }
        grid_barrier(gridDim.x);
    }
}

// ---------------------------------------------------------------------------
__global__ void final_state_kernel(float* __restrict__ out) {
    int i = blockIdx.x * blockDim.x + threadIdx.x;
    if (i < 2 * BB * 2 * MM) {
        int l = i / (BB * 2 * MM);
        int r = i % (BB * 2 * MM);
        int b = r / (2 * MM);
        int mm = r % (2 * MM);
        float v = (mm < MM) ? g_cfin[l * BB * MM + b * MM + mm]
                            : g_hfin[l * BB * MM + b * MM + (mm - MM)];
        out[i] = v;
    }
}

// ---------------------------------------------------------------------------
extern "C" void kernel_launch(void* const* d_in, const int* in_sizes, int n_in,
                              void* d_out, int out_size) {
    const float* x      = (const float*)d_in[0];
    const float* state0 = (const float*)d_in[1];
    const float* state1 = (const float*)d_in[2];
    const float* W0     = (const float*)d_in[3];
    const float* b0     = (const float*)d_in[4];
    const float* W1     = (const float*)d_in[5];
    const float* b1     = (const float*)d_in[6];
    const float* W_out  = (const float*)d_in[7];
    const float* b_out  = (const float*)d_in[8];
    float* out = (float*)d_out;

    float *pre, *cfin, *hfin;
    cudaGetSymbolAddress((void**)&pre,  g_pre);
    cudaGetSymbolAddress((void**)&cfin, g_cfin);
    cudaGetSymbolAddress((void**)&hfin, g_hfin);
    __nv_bfloat16 *Ahi, *Alo, *h0h, *h0l;
    __nv_bfloat16 *Wt0h, *Wt0l, *Wt1h, *Wt1l, *WtOh, *WtOl;
    __nv_bfloat16 *Wh0h, *Wh0l, *Wh1h, *Wh1l;
    cudaGetSymbolAddress((void**)&Ahi,  g_Ahi);
    cudaGetSymbolAddress((void**)&Alo,  g_Alo);
    cudaGetSymbolAddress((void**)&h0h,  g_h0h);
    cudaGetSymbolAddress((void**)&h0l,  g_h0l);
    cudaGetSymbolAddress((void**)&Wt0h, g_Wt0hi);
    cudaGetSymbolAddress((void**)&Wt0l, g_Wt0lo);
    cudaGetSymbolAddress((void**)&Wt1h, g_Wt1hi);
    cudaGetSymbolAddress((void**)&Wt1l, g_Wt1lo);
    cudaGetSymbolAddress((void**)&WtOh, g_WtOhi);
    cudaGetSymbolAddress((void**)&WtOl, g_WtOlo);
    cudaGetSymbolAddress((void**)&Wh0h, g_Wh0hi);
    cudaGetSymbolAddress((void**)&Wh0l, g_Wh0lo);
    cudaGetSymbolAddress((void**)&Wh1h, g_Wh1hi);
    cudaGetSymbolAddress((void**)&Wh1l, g_Wh1lo);

    cudaFuncSetAttribute(gemmT_kernel,
                         cudaFuncAttributeMaxDynamicSharedMemorySize, GT_SMEM);
    cudaFuncSetAttribute(lstm_mma_persistent,
                         cudaFuncAttributeMaxDynamicSharedMemorySize, RK_SMEM);

    // weight preps (transpose + split)
    transpose_split_kernel<<<dim3(G4 / 32, VV / 32), 256>>>(W0, G4, Wt0h, Wt0l, VV, G4);
    transpose_split_kernel<<<dim3(G4 / 32, MM / 32), 256>>>(W1, G4, Wt1h, Wt1l, MM, G4);
    transpose_split_kernel<<<dim3(VV / 32, MM / 32), 256>>>(W_out, VV, WtOh, WtOl, MM, VV);
    transpose_split_kernel<<<dim3(G4 / 32, MM / 32), 256>>>(
        W0 + (size_t)VV * G4, G4, Wh0h, Wh0l, MM, G4);
    transpose_split_kernel<<<dim3(G4 / 32, MM / 32), 256>>>(
        W1 + (size_t)MM * G4, G4, Wh1h, Wh1l, MM, G4);

    // pre0 = x @ W0x + b0
    size_t nx = (size_t)BB * TT * VV;
    split_kernel<<<(unsigned)((nx + 255) / 256), 256>>>(x, Ahi, Alo, nx);
    gemmT_kernel<<<dim3(G4 / 128, (BB * TT) / 128), 256, GT_SMEM>>>(
        Ahi, Alo, Wt0h, Wt0l, b0, pre, VV, G4);

    // layer 0 recurrence (writes h0 splits into Ahi/Alo)
    split_state_h<<<(BB * MM + 255) / 256, 256>>>(state0, h0h, h0l);
    lstm_mma_persistent<<<128, 256, RK_SMEM>>>(
        state0, Wh0h, Wh0l, h0h, h0l, pre, Ahi, Alo, cfin, hfin);

    // pre1 = h0_seq @ W1x + b1
    gemmT_kernel<<<dim3(G4 / 128, (BB * TT) / 128), 256, GT_SMEM>>>(
        Ahi, Alo, Wt1h, Wt1l, b1, pre, MM, G4);

    // layer 1 recurrence
    split_state_h<<<(BB * MM + 255) / 256, 256>>>(state1, h0h, h0l);
    lstm_mma_persistent<<<128, 256, RK_SMEM>>>(
        state1, Wh1h, Wh1l, h0h, h0l, pre, Ahi, Alo,
        cfin + BB * MM, hfin + BB * MM);

    // outputs = h1_seq @ W_out + b_out
    gemmT_kernel<<<dim3(VV / 128, (BB * TT) / 128), 256, GT_SMEM>>>(
        Ahi, Alo, WtOh, WtOl, b_out, out, MM, VV);

    final_state_kernel<<<(2 * BB * 2 * MM + 255) / 256, 256>>>(
        out + (size_t)BB * TT * VV);
}